// round 2
// baseline (speedup 1.0000x reference)
#include <cuda_runtime.h>

#define NN 50000
#define EE 800000
#define TT (EE + NN)
#define HH 4
#define CHN 256        // H * C (both layers)
#define C2  64

// ---------------- scratch (device globals; no allocation allowed) ----------
__device__ __align__(16) float g_h[(size_t)NN * CHN];   // GEMM output
__device__ __align__(16) float g_x1[(size_t)NN * CHN];  // relu(layer1 out) = layer2 in
__device__ __align__(16) float g_as[NN * HH];
__device__ __align__(16) float g_ad[NN * HH];
__device__ __align__(16) float g_e[(size_t)TT * HH];    // per-edge attention logits
__device__ int   g_deg[NN];
__device__ int   g_rowptr[NN + 1];
__device__ int   g_cursor[NN];
__device__ int   g_srcs[TT];                // CSR (by dst): source node
__device__ int   g_eids[TT];                // CSR: original edge id (for g_e lookup)

// ---------------- CSR build -------------------------------------------------
__global__ void k_zero_deg() {
    int i = blockIdx.x * blockDim.x + threadIdx.x;
    if (i < NN) g_deg[i] = 0;
}

__global__ void k_hist(const int* __restrict__ ei) {
    int t = blockIdx.x * blockDim.x + threadIdx.x;
    if (t >= TT) return;
    int d = (t < EE) ? ei[EE + t] : (t - EE);
    atomicAdd(&g_deg[d], 1);
}

__global__ void k_scan() {
    __shared__ int s[1024];
    const int tid = threadIdx.x;
    const int CHK = (NN + 1023) / 1024;
    int start = tid * CHK;
    int end   = min(start + CHK, NN);
    int sum = 0;
    for (int i = start; i < end; i++) sum += g_deg[i];
    s[tid] = sum;
    __syncthreads();
    for (int off = 1; off < 1024; off <<= 1) {
        int v = (tid >= off) ? s[tid - off] : 0;
        __syncthreads();
        s[tid] += v;
        __syncthreads();
    }
    int run = s[tid] - sum;   // exclusive prefix for this chunk
    for (int i = start; i < end; i++) {
        g_rowptr[i] = run;
        g_cursor[i] = run;
        run += g_deg[i];
    }
    if (tid == 1023) g_rowptr[NN] = s[1023];
}

__global__ void k_scatter(const int* __restrict__ ei) {
    int t = blockIdx.x * blockDim.x + threadIdx.x;
    if (t >= TT) return;
    int sv, dv;
    if (t < EE) { sv = ei[t]; dv = ei[EE + t]; }
    else        { sv = dv = t - EE; }
    int pos = atomicAdd(&g_cursor[dv], 1);
    g_srcs[pos] = sv;
    g_eids[pos] = t;
}

// ---------------- GEMM: C[M,256] = A[M,K] @ B[K,256] ------------------------
// BM=128, BN=64, BK=16; 256 threads; 8x4 micro-tile per thread.
__global__ void __launch_bounds__(256) k_gemm(const float* __restrict__ Aext,
                                              const float* __restrict__ B,
                                              int M, int K, int layer) {
    const float* __restrict__ A = (layer == 1) ? Aext : (const float*)g_x1;
    float* __restrict__ Cm = g_h;

    const int BM = 128, BN = 64, BK = 16;
    __shared__ float As[BK * BM];   // As[k][m]
    __shared__ float Bs[BK * BN];   // Bs[k][n]

    const int tid = threadIdx.x;
    const int tx = tid & 15;        // 16 cols of 4
    const int ty = tid >> 4;        // 16 rows of 8
    const int m0 = blockIdx.y * BM;
    const int n0 = blockIdx.x * BN;

    float acc[8][4];
#pragma unroll
    for (int i = 0; i < 8; i++)
#pragma unroll
        for (int j = 0; j < 4; j++) acc[i][j] = 0.f;

    for (int k0 = 0; k0 < K; k0 += BK) {
        // A tile: 128 rows x 16 cols = 512 float4 / 256 threads = 2 each
#pragma unroll
        for (int i = 0; i < 2; i++) {
            int l = tid * 2 + i;                 // 0..511
            int row = l >> 2;
            int kk = (l & 3) * 4;
            float4 a = make_float4(0.f, 0.f, 0.f, 0.f);
            if (m0 + row < M)
                a = *(const float4*)&A[(size_t)(m0 + row) * K + k0 + kk];
            As[(kk + 0) * BM + row] = a.x;
            As[(kk + 1) * BM + row] = a.y;
            As[(kk + 2) * BM + row] = a.z;
            As[(kk + 3) * BM + row] = a.w;
        }
        // B tile: 16 rows x 64 cols = 256 float4 / 256 threads = 1 each
        {
            int row = tid >> 4;
            int col = (tid & 15) * 4;
            float4 b = *(const float4*)&B[(size_t)(k0 + row) * CHN + n0 + col];
            *(float4*)&Bs[row * BN + col] = b;
        }
        __syncthreads();
#pragma unroll
        for (int kk = 0; kk < BK; kk++) {
            float a[8], b[4];
#pragma unroll
            for (int i = 0; i < 8; i++) a[i] = As[kk * BM + ty * 8 + i];
#pragma unroll
            for (int j = 0; j < 4; j++) b[j] = Bs[kk * BN + tx * 4 + j];
#pragma unroll
            for (int i = 0; i < 8; i++)
#pragma unroll
                for (int j = 0; j < 4; j++) acc[i][j] += a[i] * b[j];
        }
        __syncthreads();
    }
#pragma unroll
    for (int i = 0; i < 8; i++) {
        int row = m0 + ty * 8 + i;
        if (row < M)
            *(float4*)&Cm[(size_t)row * CHN + n0 + tx * 4] =
                make_float4(acc[i][0], acc[i][1], acc[i][2], acc[i][3]);
    }
}

// ---------------- alpha_src / alpha_dst per (node, head) --------------------
// one warp per (n, h): dot over 64 channels
__global__ void k_alpha(const float* __restrict__ att_s,
                        const float* __restrict__ att_d) {
    int w = (blockIdx.x * blockDim.x + threadIdx.x) >> 5;
    int lane = threadIdx.x & 31;
    if (w >= NN * HH) return;
    int n = w >> 2, hh = w & 3;
    const float* row = g_h + (size_t)n * CHN + hh * 64;
    float v1 = row[lane], v2 = row[lane + 32];
    float s = v1 * att_s[hh * 64 + lane] + v2 * att_s[hh * 64 + lane + 32];
    float d = v1 * att_d[hh * 64 + lane] + v2 * att_d[hh * 64 + lane + 32];
#pragma unroll
    for (int o = 16; o; o >>= 1) {
        s += __shfl_xor_sync(0xffffffffu, s, o);
        d += __shfl_xor_sync(0xffffffffu, d, o);
    }
    if (lane == 0) { g_as[w] = s; g_ad[w] = d; }
}

// ---------------- per-edge logits e = leaky_relu(as[src]+ad[dst]) -----------
__device__ __forceinline__ float lrelu(float v) { return v > 0.f ? v : 0.2f * v; }

__global__ void k_edge(const int* __restrict__ ei) {
    int t = blockIdx.x * blockDim.x + threadIdx.x;
    if (t >= TT) return;
    int sv, dv;
    if (t < EE) { sv = ei[t]; dv = ei[EE + t]; }
    else        { sv = dv = t - EE; }
    float4 as = *(const float4*)&g_as[sv * 4];
    float4 ad = *(const float4*)&g_ad[dv * 4];
    float4 e;
    e.x = lrelu(as.x + ad.x);
    e.y = lrelu(as.y + ad.y);
    e.z = lrelu(as.z + ad.z);
    e.w = lrelu(as.w + ad.w);
    *(float4*)&g_e[(size_t)t * 4] = e;
}

// ---------------- per-node softmax + aggregation (block per node) -----------
// LAYER==1: out = g_x1, epilogue relu(acc + b1[ch])
// LAYER==2: out = d_out, epilogue mean over heads + b2
template <int LAYER>
__global__ void __launch_bounds__(256) k_agg(const float* __restrict__ bias,
                                             float* __restrict__ outext) {
    const int n = blockIdx.x;
    const int tid = threadIdx.x;
    __shared__ float sh_m[4], sh_inv[4];
    __shared__ float s_alpha[64 * 4];
    __shared__ int s_src[64];
    __shared__ float s_acc[256];

    const int row = g_rowptr[n];
    const int deg = g_rowptr[n + 1] - row;
    const int wid = tid >> 5, lane = tid & 31;

    if (wid < 4) {
        float m = -1e30f;
        for (int j = lane; j < deg; j += 32)
            m = fmaxf(m, g_e[(size_t)g_eids[row + j] * 4 + wid]);
#pragma unroll
        for (int o = 16; o; o >>= 1) m = fmaxf(m, __shfl_xor_sync(0xffffffffu, m, o));
        float s = 0.f;
        for (int j = lane; j < deg; j += 32)
            s += __expf(g_e[(size_t)g_eids[row + j] * 4 + wid] - m);
#pragma unroll
        for (int o = 16; o; o >>= 1) s += __shfl_xor_sync(0xffffffffu, s, o);
        if (lane == 0) { sh_m[wid] = m; sh_inv[wid] = 1.f / (s + 1e-16f); }
    }
    __syncthreads();

    const float* __restrict__ hin = g_h;
    float acc = 0.f;
    const int head = tid >> 6;
    for (int c0 = 0; c0 < deg; c0 += 64) {
        int cn = min(64, deg - c0);
        if (tid < cn * 4) {
            int j = tid >> 2, hh = tid & 3;
            int id = g_eids[row + c0 + j];
            s_alpha[tid] = __expf(g_e[(size_t)id * 4 + hh] - sh_m[hh]) * sh_inv[hh];
        }
        if (tid < cn) s_src[tid] = g_srcs[row + c0 + tid];
        __syncthreads();
        for (int j = 0; j < cn; j++)
            acc += s_alpha[j * 4 + head] * hin[(size_t)s_src[j] * CHN + tid];
        __syncthreads();
    }

    if (LAYER == 1) {
        g_x1[(size_t)n * CHN + tid] = fmaxf(acc + bias[tid], 0.f);
    } else {
        s_acc[tid] = acc;
        __syncthreads();
        if (tid < 64)
            outext[(size_t)n * C2 + tid] =
                0.25f * (s_acc[tid] + s_acc[64 + tid] + s_acc[128 + tid] + s_acc[192 + tid]) +
                bias[tid];
    }
}

// ---------------- launch -----------------------------------------------------
extern "C" void kernel_launch(void* const* d_in, const int* in_sizes, int n_in,
                              void* d_out, int out_size) {
    const float* x   = (const float*)d_in[0];
    const int*   ei  = (const int*)d_in[1];
    const float* W1  = (const float*)d_in[2];
    const float* as1 = (const float*)d_in[3];
    const float* ad1 = (const float*)d_in[4];
    const float* b1  = (const float*)d_in[5];
    const float* W2  = (const float*)d_in[6];
    const float* as2 = (const float*)d_in[7];
    const float* ad2 = (const float*)d_in[8];
    const float* b2  = (const float*)d_in[9];
    float* out = (float*)d_out;

    // CSR build (shared by both layers)
    k_zero_deg<<<(NN + 255) / 256, 256>>>();
    k_hist<<<(TT + 255) / 256, 256>>>(ei);
    k_scan<<<1, 1024>>>();
    k_scatter<<<(TT + 255) / 256, 256>>>(ei);

    dim3 gemm_grid(CHN / 64, (NN + 127) / 128);
    int alpha_blocks = (NN * HH * 32 + 255) / 256;

    // ----- layer 1 -----
    k_gemm<<<gemm_grid, 256>>>(x, W1, NN, 128, 1);
    k_alpha<<<alpha_blocks, 256>>>(as1, ad1);
    k_edge<<<(TT + 255) / 256, 256>>>(ei);
    k_agg<1><<<NN, 256>>>(b1, nullptr);

    // ----- layer 2 -----
    k_gemm<<<gemm_grid, 256>>>(nullptr, W2, NN, 256, 2);
    k_alpha<<<alpha_blocks, 256>>>(as2, ad2);
    k_edge<<<(TT + 255) / 256, 256>>>(ei);
    k_agg<2><<<NN, 256>>>(b2, out);
}

// round 3
// speedup vs baseline: 1.1234x; 1.1234x over previous
#include <cuda_runtime.h>
#include <mma.h>
using namespace nvcuda;

#define NN 50000
#define NPAD 50048     // NN rounded up to 128 (GEMM tile)
#define EE 800000
#define TT (EE + NN)
#define HH 4
#define CHN 256        // H * C (both layers)
#define C2  64

// ---------------- scratch (device globals; no allocation allowed) ----------
__device__ __align__(16) float g_h[(size_t)NPAD * CHN];   // GEMM output
__device__ __align__(16) float g_x1[(size_t)NPAD * CHN];  // relu(layer1 out)
__device__ __align__(16) float g_as[NN * HH];
__device__ __align__(16) float g_ad[NN * HH];
__device__ __align__(16) float g_e[(size_t)TT * HH];      // CSR-ordered logits
__device__ int   g_deg[NN];
__device__ int   g_rowptr[NN + 1];
__device__ int   g_cursor[NN];
__device__ int   g_srcs[TT];                // CSR (by dst): source node
__device__ int   g_dsts[TT];                // CSR: destination node

// ---------------- CSR build -------------------------------------------------
__global__ void k_zero_deg() {
    int i = blockIdx.x * blockDim.x + threadIdx.x;
    if (i < NN) g_deg[i] = 0;
}

__global__ void k_hist(const int* __restrict__ ei) {
    int t = blockIdx.x * blockDim.x + threadIdx.x;
    if (t >= TT) return;
    int d = (t < EE) ? ei[EE + t] : (t - EE);
    atomicAdd(&g_deg[d], 1);
}

__global__ void k_scan() {
    __shared__ int s[1024];
    const int tid = threadIdx.x;
    const int CHK = (NN + 1023) / 1024;
    int start = tid * CHK;
    int end   = min(start + CHK, NN);
    int sum = 0;
    for (int i = start; i < end; i++) sum += g_deg[i];
    s[tid] = sum;
    __syncthreads();
    for (int off = 1; off < 1024; off <<= 1) {
        int v = (tid >= off) ? s[tid - off] : 0;
        __syncthreads();
        s[tid] += v;
        __syncthreads();
    }
    int run = s[tid] - sum;   // exclusive prefix for this chunk
    for (int i = start; i < end; i++) {
        g_rowptr[i] = run;
        g_cursor[i] = run;
        run += g_deg[i];
    }
    if (tid == 1023) g_rowptr[NN] = s[1023];
}

__global__ void k_scatter(const int* __restrict__ ei) {
    int t = blockIdx.x * blockDim.x + threadIdx.x;
    if (t >= TT) return;
    int sv, dv;
    if (t < EE) { sv = ei[t]; dv = ei[EE + t]; }
    else        { sv = dv = t - EE; }
    int pos = atomicAdd(&g_cursor[dv], 1);
    g_srcs[pos] = sv;
    g_dsts[pos] = dv;
}

// ---------------- tf32 tensor-core GEMM: C[M,256] = A[M,K] @ B[K,256] -------
// BM=128, BN=64, BK=16; 8 warps in 4x2; each warp 32x32 via 2x2 m16n16k8 frags.
__global__ void __launch_bounds__(256) k_gemm(const float* __restrict__ Aext,
                                              const float* __restrict__ B,
                                              int M, int K, int layer) {
    const float* __restrict__ A = (layer == 1) ? Aext : (const float*)g_x1;

    __shared__ __align__(16) float As[128 * 16];
    __shared__ __align__(16) float Bs[16 * 64];

    const int tid = threadIdx.x;
    const int wid = tid >> 5;
    const int wm = wid >> 1;      // 0..3
    const int wn = wid & 1;       // 0..1
    const int m0 = blockIdx.y * 128;
    const int n0 = blockIdx.x * 64;

    wmma::fragment<wmma::accumulator, 16, 16, 8, float> c[2][2];
#pragma unroll
    for (int i = 0; i < 2; i++)
#pragma unroll
        for (int j = 0; j < 2; j++) wmma::fill_fragment(c[i][j], 0.f);

    for (int k0 = 0; k0 < K; k0 += 16) {
        // A tile: 128 rows x 16 cols = 512 float4; 2 per thread
#pragma unroll
        for (int i = 0; i < 2; i++) {
            int l = tid + i * 256;             // 0..511
            int row = l >> 2;
            int c4 = (l & 3) * 4;
            float4 v = make_float4(0.f, 0.f, 0.f, 0.f);
            if (m0 + row < M)
                v = *(const float4*)&A[(size_t)(m0 + row) * K + k0 + c4];
            *(float4*)&As[row * 16 + c4] = v;
        }
        // B tile: 16 rows x 64 cols = 256 float4; 1 per thread
        {
            int row = tid >> 4;
            int col = (tid & 15) * 4;
            *(float4*)&Bs[row * 64 + col] =
                *(const float4*)&B[(size_t)(k0 + row) * CHN + n0 + col];
        }
        __syncthreads();
#pragma unroll
        for (int kk = 0; kk < 16; kk += 8) {
            wmma::fragment<wmma::matrix_a, 16, 16, 8, wmma::precision::tf32, wmma::row_major> a[2];
            wmma::fragment<wmma::matrix_b, 16, 16, 8, wmma::precision::tf32, wmma::row_major> b[2];
#pragma unroll
            for (int i = 0; i < 2; i++) {
                wmma::load_matrix_sync(a[i], &As[(wm * 32 + i * 16) * 16 + kk], 16);
#pragma unroll
                for (int e = 0; e < a[i].num_elements; e++)
                    a[i].x[e] = wmma::__float_to_tf32(a[i].x[e]);
            }
#pragma unroll
            for (int j = 0; j < 2; j++) {
                wmma::load_matrix_sync(b[j], &Bs[kk * 64 + wn * 32 + j * 16], 64);
#pragma unroll
                for (int e = 0; e < b[j].num_elements; e++)
                    b[j].x[e] = wmma::__float_to_tf32(b[j].x[e]);
            }
#pragma unroll
            for (int i = 0; i < 2; i++)
#pragma unroll
                for (int j = 0; j < 2; j++)
                    wmma::mma_sync(c[i][j], a[i], b[j], c[i][j]);
        }
        __syncthreads();
    }
    // store (g_h padded to NPAD rows, so unguarded store is safe)
#pragma unroll
    for (int i = 0; i < 2; i++)
#pragma unroll
        for (int j = 0; j < 2; j++)
            wmma::store_matrix_sync(
                &g_h[(size_t)(m0 + wm * 32 + i * 16) * CHN + n0 + wn * 32 + j * 16],
                c[i][j], CHN, wmma::mem_row_major);
}

// ---------------- alpha_src / alpha_dst per (node, head) --------------------
__global__ void k_alpha(const float* __restrict__ att_s,
                        const float* __restrict__ att_d) {
    int w = (blockIdx.x * blockDim.x + threadIdx.x) >> 5;
    int lane = threadIdx.x & 31;
    if (w >= NN * HH) return;
    int n = w >> 2, hh = w & 3;
    const float* row = g_h + (size_t)n * CHN + hh * 64;
    float v1 = row[lane], v2 = row[lane + 32];
    float s = v1 * att_s[hh * 64 + lane] + v2 * att_s[hh * 64 + lane + 32];
    float d = v1 * att_d[hh * 64 + lane] + v2 * att_d[hh * 64 + lane + 32];
#pragma unroll
    for (int o = 16; o; o >>= 1) {
        s += __shfl_xor_sync(0xffffffffu, s, o);
        d += __shfl_xor_sync(0xffffffffu, d, o);
    }
    if (lane == 0) { g_as[w] = s; g_ad[w] = d; }
}

// ---------------- per-edge logits, CSR order ---------------------------------
__device__ __forceinline__ float lrelu(float v) { return v > 0.f ? v : 0.2f * v; }

__global__ void k_edge() {
    int p = blockIdx.x * blockDim.x + threadIdx.x;
    if (p >= TT) return;
    int sv = g_srcs[p], dv = g_dsts[p];
    float4 as = *(const float4*)&g_as[sv * 4];
    float4 ad = *(const float4*)&g_ad[dv * 4];
    float4 e;
    e.x = lrelu(as.x + ad.x);
    e.y = lrelu(as.y + ad.y);
    e.z = lrelu(as.z + ad.z);
    e.w = lrelu(as.w + ad.w);
    *(float4*)&g_e[(size_t)p * 4] = e;
}

// ---------------- per-node softmax + aggregation (block per node) -----------
template <int LAYER>
__global__ void __launch_bounds__(256) k_agg(const float* __restrict__ bias,
                                             float* __restrict__ outext) {
    const int n = blockIdx.x;
    const int tid = threadIdx.x;
    __shared__ float sh_m[4], sh_inv[4];
    __shared__ float s_alpha[64 * 4];
    __shared__ int s_src[64];
    __shared__ float s_acc[256];

    const int row = g_rowptr[n];
    const int deg = g_rowptr[n + 1] - row;
    const int wid = tid >> 5, lane = tid & 31;

    if (wid < 4) {
        float m = -1e30f;
        for (int j = lane; j < deg; j += 32)
            m = fmaxf(m, g_e[(size_t)(row + j) * 4 + wid]);
#pragma unroll
        for (int o = 16; o; o >>= 1) m = fmaxf(m, __shfl_xor_sync(0xffffffffu, m, o));
        float s = 0.f;
        for (int j = lane; j < deg; j += 32)
            s += __expf(g_e[(size_t)(row + j) * 4 + wid] - m);
#pragma unroll
        for (int o = 16; o; o >>= 1) s += __shfl_xor_sync(0xffffffffu, s, o);
        if (lane == 0) { sh_m[wid] = m; sh_inv[wid] = 1.f / (s + 1e-16f); }
    }
    __syncthreads();

    const float* __restrict__ hin = g_h;
    float acc0 = 0.f, acc1 = 0.f, acc2 = 0.f, acc3 = 0.f;
    const int head = tid >> 6;
    for (int c0 = 0; c0 < deg; c0 += 64) {
        int cn = min(64, deg - c0);
        if (tid < cn * 4) {
            int j = tid >> 2, hh = tid & 3;
            s_alpha[tid] = __expf(g_e[(size_t)(row + c0 + j) * 4 + hh] - sh_m[hh]) * sh_inv[hh];
        }
        if (tid < cn) s_src[tid] = g_srcs[row + c0 + tid];
        __syncthreads();
        int j = 0;
        for (; j + 3 < cn; j += 4) {
            int s0 = s_src[j], s1 = s_src[j + 1], s2 = s_src[j + 2], s3 = s_src[j + 3];
            acc0 += s_alpha[(j + 0) * 4 + head] * hin[(size_t)s0 * CHN + tid];
            acc1 += s_alpha[(j + 1) * 4 + head] * hin[(size_t)s1 * CHN + tid];
            acc2 += s_alpha[(j + 2) * 4 + head] * hin[(size_t)s2 * CHN + tid];
            acc3 += s_alpha[(j + 3) * 4 + head] * hin[(size_t)s3 * CHN + tid];
        }
        for (; j < cn; j++)
            acc0 += s_alpha[j * 4 + head] * hin[(size_t)s_src[j] * CHN + tid];
        __syncthreads();
    }
    float acc = (acc0 + acc1) + (acc2 + acc3);

    if (LAYER == 1) {
        g_x1[(size_t)n * CHN + tid] = fmaxf(acc + bias[tid], 0.f);
    } else {
        s_acc[tid] = acc;
        __syncthreads();
        if (tid < 64)
            outext[(size_t)n * C2 + tid] =
                0.25f * (s_acc[tid] + s_acc[64 + tid] + s_acc[128 + tid] + s_acc[192 + tid]) +
                bias[tid];
    }
}

// ---------------- launch -----------------------------------------------------
extern "C" void kernel_launch(void* const* d_in, const int* in_sizes, int n_in,
                              void* d_out, int out_size) {
    const float* x   = (const float*)d_in[0];
    const int*   ei  = (const int*)d_in[1];
    const float* W1  = (const float*)d_in[2];
    const float* as1 = (const float*)d_in[3];
    const float* ad1 = (const float*)d_in[4];
    const float* b1  = (const float*)d_in[5];
    const float* W2  = (const float*)d_in[6];
    const float* as2 = (const float*)d_in[7];
    const float* ad2 = (const float*)d_in[8];
    const float* b2  = (const float*)d_in[9];
    float* out = (float*)d_out;

    // CSR build (shared by both layers)
    k_zero_deg<<<(NN + 255) / 256, 256>>>();
    k_hist<<<(TT + 255) / 256, 256>>>(ei);
    k_scan<<<1, 1024>>>();
    k_scatter<<<(TT + 255) / 256, 256>>>(ei);

    dim3 gemm_grid(CHN / 64, NPAD / 128);
    int alpha_blocks = (NN * HH * 32 + 255) / 256;

    // ----- layer 1 -----
    k_gemm<<<gemm_grid, 256>>>(x, W1, NN, 128, 1);
    k_alpha<<<alpha_blocks, 256>>>(as1, ad1);
    k_edge<<<(TT + 255) / 256, 256>>>();
    k_agg<1><<<NN, 256>>>(b1, nullptr);

    // ----- layer 2 -----
    k_gemm<<<gemm_grid, 256>>>(nullptr, W2, NN, 256, 2);
    k_alpha<<<alpha_blocks, 256>>>(as2, ad2);
    k_edge<<<(TT + 255) / 256, 256>>>();
    k_agg<2><<<NN, 256>>>(b2, out);
}

// round 5
// speedup vs baseline: 1.3896x; 1.2370x over previous
#include <cuda_runtime.h>
#include <mma.h>
using namespace nvcuda;

#define NN 50000
#define NPAD 50048     // NN rounded up to 128 (GEMM tile)
#define EE 800000
#define TT (EE + NN)
#define HH 4
#define CHN 256        // H * C (both layers)
#define C2  64

// ---------------- scratch (device globals; no allocation allowed) ----------
__device__ __align__(16) float g_h[(size_t)NPAD * CHN];   // GEMM output
__device__ __align__(16) float g_x1[(size_t)NPAD * CHN];  // relu(layer1 out)
__device__ __align__(16) float g_as[NN * HH];
__device__ __align__(16) float g_ad[NN * HH];
__device__ __align__(16) float g_e[(size_t)TT * HH];      // CSR-ordered logits
__device__ int   g_deg[NN];
__device__ int   g_rowptr[NN + 1];
__device__ int   g_cursor[NN];
__device__ int   g_srcs[TT];                // CSR (by dst): source node
__device__ int   g_dsts[TT];                // CSR: destination node

// ---------------- CSR build -------------------------------------------------
__global__ void k_zero_deg() {
    int i = blockIdx.x * blockDim.x + threadIdx.x;
    if (i < NN) g_deg[i] = 0;
}

__global__ void k_hist(const int* __restrict__ ei) {
    int t = blockIdx.x * blockDim.x + threadIdx.x;
    if (t >= TT) return;
    int d = (t < EE) ? ei[EE + t] : (t - EE);
    atomicAdd(&g_deg[d], 1);
}

__global__ void k_scan() {
    __shared__ int s[1024];
    const int tid = threadIdx.x;
    const int CHK = (NN + 1023) / 1024;
    int start = tid * CHK;
    int end   = min(start + CHK, NN);
    int sum = 0;
    for (int i = start; i < end; i++) sum += g_deg[i];
    s[tid] = sum;
    __syncthreads();
    for (int off = 1; off < 1024; off <<= 1) {
        int v = (tid >= off) ? s[tid - off] : 0;
        __syncthreads();
        s[tid] += v;
        __syncthreads();
    }
    int run = s[tid] - sum;   // exclusive prefix for this chunk
    for (int i = start; i < end; i++) {
        g_rowptr[i] = run;
        g_cursor[i] = run;
        run += g_deg[i];
    }
    if (tid == 1023) g_rowptr[NN] = s[1023];
}

__global__ void k_scatter(const int* __restrict__ ei) {
    int t = blockIdx.x * blockDim.x + threadIdx.x;
    if (t >= TT) return;
    int sv, dv;
    if (t < EE) { sv = ei[t]; dv = ei[EE + t]; }
    else        { sv = dv = t - EE; }
    int pos = atomicAdd(&g_cursor[dv], 1);
    g_srcs[pos] = sv;
    g_dsts[pos] = dv;
}

// ---------------- tf32 tensor-core GEMM: C[M,256] = A[M,K] @ B[K,256] -------
// BM=128, BN=64, BK=32; single smem buffer + register prefetch;
// tf32 pre-converted at fill. 8 warps 4x2; each warp 32x32 via 2x2 m16n16k8.
#define BM 128
#define BN 64
#define BK 32
#define LDA (BK + 4)   // 36 floats (mult of 4 -> 16B rows)
#define LDB (BN + 4)   // 68 floats

__global__ void __launch_bounds__(256) k_gemm(const float* __restrict__ Aext,
                                              const float* __restrict__ B,
                                              int M, int K, int layer) {
    const float* __restrict__ A = (layer == 1) ? Aext : (const float*)g_x1;

    __shared__ __align__(16) float As[BM][LDA];   // 18432 B
    __shared__ __align__(16) float Bs[BK][LDB];   //  8704 B

    const int tid = threadIdx.x;
    const int wid = tid >> 5;
    const int wm = wid >> 1;      // 0..3
    const int wn = wid & 1;       // 0..1
    const int m0 = blockIdx.y * BM;
    const int n0 = blockIdx.x * BN;

    // per-thread load coords
    const int arow[4] = { (tid + 0) >> 3, (tid + 256) >> 3, (tid + 512) >> 3, (tid + 768) >> 3 };
    const int acol = (tid & 7) * 4;
    const int brow[2] = { (tid + 0) >> 4, (tid + 256) >> 4 };
    const int bcol = (tid & 15) * 4;

    float4 ra[4], rb[2];

    auto loadG = [&](int k0) {
#pragma unroll
        for (int i = 0; i < 4; i++) {
            float4 v = make_float4(0.f, 0.f, 0.f, 0.f);
            if (m0 + arow[i] < M)
                v = *(const float4*)&A[(size_t)(m0 + arow[i]) * K + k0 + acol];
            ra[i] = v;
        }
#pragma unroll
        for (int i = 0; i < 2; i++)
            rb[i] = *(const float4*)&B[(size_t)(k0 + brow[i]) * CHN + n0 + bcol];
    };
    auto storeS = [&]() {
#pragma unroll
        for (int i = 0; i < 4; i++) {
            float* p = &As[arow[i]][acol];
            p[0] = wmma::__float_to_tf32(ra[i].x);
            p[1] = wmma::__float_to_tf32(ra[i].y);
            p[2] = wmma::__float_to_tf32(ra[i].z);
            p[3] = wmma::__float_to_tf32(ra[i].w);
        }
#pragma unroll
        for (int i = 0; i < 2; i++) {
            float* p = &Bs[brow[i]][bcol];
            p[0] = wmma::__float_to_tf32(rb[i].x);
            p[1] = wmma::__float_to_tf32(rb[i].y);
            p[2] = wmma::__float_to_tf32(rb[i].z);
            p[3] = wmma::__float_to_tf32(rb[i].w);
        }
    };

    wmma::fragment<wmma::accumulator, 16, 16, 8, float> c[2][2];
#pragma unroll
    for (int i = 0; i < 2; i++)
#pragma unroll
        for (int j = 0; j < 2; j++) wmma::fill_fragment(c[i][j], 0.f);

    loadG(0);
    storeS();
    __syncthreads();

    for (int k0 = 0; k0 < K; k0 += BK) {
        const bool has_next = (k0 + BK) < K;
        if (has_next) loadG(k0 + BK);   // prefetch into registers

#pragma unroll
        for (int kk = 0; kk < BK; kk += 8) {
            wmma::fragment<wmma::matrix_a, 16, 16, 8, wmma::precision::tf32, wmma::row_major> a[2];
            wmma::fragment<wmma::matrix_b, 16, 16, 8, wmma::precision::tf32, wmma::row_major> b[2];
#pragma unroll
            for (int i = 0; i < 2; i++)
                wmma::load_matrix_sync(a[i], &As[wm * 32 + i * 16][kk], LDA);
#pragma unroll
            for (int j = 0; j < 2; j++)
                wmma::load_matrix_sync(b[j], &Bs[kk][wn * 32 + j * 16], LDB);
#pragma unroll
            for (int i = 0; i < 2; i++)
#pragma unroll
                for (int j = 0; j < 2; j++)
                    wmma::mma_sync(c[i][j], a[i], b[j], c[i][j]);
        }

        if (has_next) {
            __syncthreads();
            storeS();
            __syncthreads();
        }
    }

    // store (g_h padded to NPAD rows, so unguarded store is safe)
#pragma unroll
    for (int i = 0; i < 2; i++)
#pragma unroll
        for (int j = 0; j < 2; j++)
            wmma::store_matrix_sync(
                &g_h[(size_t)(m0 + wm * 32 + i * 16) * CHN + n0 + wn * 32 + j * 16],
                c[i][j], CHN, wmma::mem_row_major);
}

// ---------------- alpha_src / alpha_dst per (node, head) --------------------
__global__ void k_alpha(const float* __restrict__ att_s,
                        const float* __restrict__ att_d) {
    int w = (blockIdx.x * blockDim.x + threadIdx.x) >> 5;
    int lane = threadIdx.x & 31;
    if (w >= NN * HH) return;
    int n = w >> 2, hh = w & 3;
    const float* row = g_h + (size_t)n * CHN + hh * 64;
    float v1 = row[lane], v2 = row[lane + 32];
    float s = v1 * att_s[hh * 64 + lane] + v2 * att_s[hh * 64 + lane + 32];
    float d = v1 * att_d[hh * 64 + lane] + v2 * att_d[hh * 64 + lane + 32];
#pragma unroll
    for (int o = 16; o; o >>= 1) {
        s += __shfl_xor_sync(0xffffffffu, s, o);
        d += __shfl_xor_sync(0xffffffffu, d, o);
    }
    if (lane == 0) { g_as[w] = s; g_ad[w] = d; }
}

// ---------------- per-edge logits, CSR order ---------------------------------
__device__ __forceinline__ float lrelu(float v) { return v > 0.f ? v : 0.2f * v; }

__global__ void k_edge() {
    int p = blockIdx.x * blockDim.x + threadIdx.x;
    if (p >= TT) return;
    int sv = g_srcs[p], dv = g_dsts[p];
    float4 as = *(const float4*)&g_as[sv * 4];
    float4 ad = *(const float4*)&g_ad[dv * 4];
    float4 e;
    e.x = lrelu(as.x + ad.x);
    e.y = lrelu(as.y + ad.y);
    e.z = lrelu(as.z + ad.z);
    e.w = lrelu(as.w + ad.w);
    *(float4*)&g_e[(size_t)p * 4] = e;
}

// ---------------- per-node softmax + aggregation (block per node) -----------
// 4 edge-slots x 64 threads x float4 channels; final 4-way smem reduce.
template <int LAYER>
__global__ void __launch_bounds__(256) k_agg(const float* __restrict__ bias,
                                             float* __restrict__ outext) {
    const int n = blockIdx.x;
    const int tid = threadIdx.x;
    __shared__ float sh_m[4], sh_inv[4];
    __shared__ float s_alpha[64 * 4];
    __shared__ int s_src[64];
    __shared__ __align__(16) float s_red[256 * 4];

    const int row = g_rowptr[n];
    const int deg = g_rowptr[n + 1] - row;
    const int wid = tid >> 5, lane = tid & 31;

    if (wid < 4) {
        float m = -1e30f;
        for (int j = lane; j < deg; j += 32)
            m = fmaxf(m, g_e[(size_t)(row + j) * 4 + wid]);
#pragma unroll
        for (int o = 16; o; o >>= 1) m = fmaxf(m, __shfl_xor_sync(0xffffffffu, m, o));
        float s = 0.f;
        for (int j = lane; j < deg; j += 32)
            s += __expf(g_e[(size_t)(row + j) * 4 + wid] - m);
#pragma unroll
        for (int o = 16; o; o >>= 1) s += __shfl_xor_sync(0xffffffffu, s, o);
        if (lane == 0) { sh_m[wid] = m; sh_inv[wid] = 1.f / (s + 1e-16f); }
    }
    __syncthreads();

    const int grp = tid >> 6;        // edge slot 0..3
    const int ch4 = tid & 63;        // float4 channel group -> channels ch4*4..+3
    const int head = ch4 >> 4;
    float4 acc = make_float4(0.f, 0.f, 0.f, 0.f);

    for (int c0 = 0; c0 < deg; c0 += 64) {
        int cn = min(64, deg - c0);
        if (tid < cn * 4) {
            int j = tid >> 2, hh = tid & 3;
            s_alpha[tid] = __expf(g_e[(size_t)(row + c0 + j) * 4 + hh] - sh_m[hh]) * sh_inv[hh];
        }
        if (tid < cn) s_src[tid] = g_srcs[row + c0 + tid];
        __syncthreads();
        for (int j = grp; j < cn; j += 4) {
            float a = s_alpha[j * 4 + head];
            const float4 hv = *(const float4*)&g_h[(size_t)s_src[j] * CHN + ch4 * 4];
            acc.x += a * hv.x;
            acc.y += a * hv.y;
            acc.z += a * hv.z;
            acc.w += a * hv.w;
        }
        __syncthreads();
    }

    // cross-slot reduce
    *(float4*)&s_red[tid * 4] = acc;
    __syncthreads();
    if (grp == 0) {
        float4 r = acc;
#pragma unroll
        for (int g2 = 1; g2 < 4; g2++) {
            const float4 o = *(const float4*)&s_red[(g2 * 64 + ch4) * 4];
            r.x += o.x; r.y += o.y; r.z += o.z; r.w += o.w;
        }
        const int c = ch4 * 4;
        if (LAYER == 1) {
            const float4 b = *(const float4*)&bias[c];
            float4 o;
            o.x = fmaxf(r.x + b.x, 0.f);
            o.y = fmaxf(r.y + b.y, 0.f);
            o.z = fmaxf(r.z + b.z, 0.f);
            o.w = fmaxf(r.w + b.w, 0.f);
            *(float4*)&g_x1[(size_t)n * CHN + c] = o;
        } else {
            *(float4*)&s_red[c] = r;   // s_red[ch] = total[ch]
        }
    }
    if (LAYER == 2) {
        __syncthreads();
        if (tid < 64)
            outext[(size_t)n * C2 + tid] =
                0.25f * (s_red[tid] + s_red[64 + tid] + s_red[128 + tid] + s_red[192 + tid]) +
                bias[tid];
    }
}

// ---------------- launch -----------------------------------------------------
extern "C" void kernel_launch(void* const* d_in, const int* in_sizes, int n_in,
                              void* d_out, int out_size) {
    const float* x   = (const float*)d_in[0];
    const int*   ei  = (const int*)d_in[1];
    const float* W1  = (const float*)d_in[2];
    const float* as1 = (const float*)d_in[3];
    const float* ad1 = (const float*)d_in[4];
    const float* b1  = (const float*)d_in[5];
    const float* W2  = (const float*)d_in[6];
    const float* as2 = (const float*)d_in[7];
    const float* ad2 = (const float*)d_in[8];
    const float* b2  = (const float*)d_in[9];
    float* out = (float*)d_out;

    // CSR build (shared by both layers)
    k_zero_deg<<<(NN + 255) / 256, 256>>>();
    k_hist<<<(TT + 255) / 256, 256>>>(ei);
    k_scan<<<1, 1024>>>();
    k_scatter<<<(TT + 255) / 256, 256>>>(ei);

    dim3 gemm_grid(CHN / BN, NPAD / BM);
    int alpha_blocks = (NN * HH * 32 + 255) / 256;

    // ----- layer 1 -----
    k_gemm<<<gemm_grid, 256>>>(x, W1, NN, 128, 1);
    k_alpha<<<alpha_blocks, 256>>>(as1, ad1);
    k_edge<<<(TT + 255) / 256, 256>>>();
    k_agg<1><<<NN, 256>>>(b1, nullptr);

    // ----- layer 2 -----
    k_gemm<<<gemm_grid, 256>>>(nullptr, W2, NN, 256, 2);
    k_alpha<<<alpha_blocks, 256>>>(as2, ad2);
    k_edge<<<(TT + 255) / 256, 256>>>();
    k_agg<2><<<NN, 256>>>(b2, out);
}